// round 17
// baseline (speedup 1.0000x reference)
#include <cuda_runtime.h>

// SplitMLP: out[b,g,o] = b2[g,o] + sum_h W2[g,o,h] * relu( b1[g,h]
//        + sum_c W1_day[g,h,c]*day[b,c] + sum_v W1_var[g,h,v]*items[b,g,v] )
// B=128, C=16, V=32, H=64, O=4, G=10000. fp32.
//
// R7: R5 register-tiled core (4b x 16h, packed f32x2) + software pipeline:
// items double-buffered in smem and prefetched one group ahead so the scattered
// 256-wavefront LDG burst drains under the fc1 compute shadow instead of
// stalling between barriers (R5: fma=49%, L1=83% -> staging serialized).

constexpr int B = 128;
constexpr int C = 16;
constexpr int V = 32;
constexpr int H = 64;
constexpr int O = 4;
constexpr int G = 10000;

constexpr int GPB = 8;
constexpr int THREADS = 128;
constexpr int KTOT = C + V;   // 48
constexpr int XS = 128;       // s_xd/s_xi row stride (floats); STS cols=tid & reads {0,4,8,12}+w*32 -> conflict-free
constexpr int WS = 68;        // s_w1/s_w2 row stride

using u64 = unsigned long long;

__device__ __forceinline__ u64 ffma2(u64 a, u64 b, u64 c) {
    u64 d;
    asm("fma.rn.f32x2 %0, %1, %2, %3;" : "=l"(d) : "l"(a), "l"(b), "l"(c));
    return d;
}
__device__ __forceinline__ u64 bcast2(float x) {
    u64 d; unsigned xi = __float_as_uint(x);
    asm("mov.b64 %0, {%1, %1};" : "=l"(d) : "r"(xi));
    return d;
}
__device__ __forceinline__ float2 unpack2(u64 a) {
    unsigned x, y;
    asm("mov.b64 {%0, %1}, %2;" : "=r"(x), "=r"(y) : "l"(a));
    return make_float2(__uint_as_float(x), __uint_as_float(y));
}
__device__ __forceinline__ u64 pack2(float x, float y) {
    u64 d; unsigned xi = __float_as_uint(x), yi = __float_as_uint(y);
    asm("mov.b64 %0, {%1, %2};" : "=l"(d) : "r"(xi), "r"(yi));
    return d;
}

__global__ void __launch_bounds__(THREADS, 4)
splitmlp_kernel(const float* __restrict__ day,     // [B][C]
                const float* __restrict__ items,   // [B][G][V]
                const float* __restrict__ W1_day,  // [G][H][C]
                const float* __restrict__ W1_var,  // [G][H][V]
                const float* __restrict__ b1,      // [G][H]
                const float* __restrict__ W2,      // [G][O][H]
                const float* __restrict__ b2,      // [G][O]
                float* __restrict__ out)           // [B][G][O]
{
    __shared__ __align__(16) float s_xd[C][XS];       // day transposed [c][b], static per CTA
    __shared__ __align__(16) float s_xi[2][V][XS];    // items transposed [v][b], double-buffered
    __shared__ __align__(16) float s_w1[KTOT][WS];    // fc1 weights [k][h]
    __shared__ __align__(16) float s_w2[O][WS];       // fc2 weights [o][h]
    __shared__ __align__(16) float s_b1[H];
    __shared__ __align__(16) float s_b2[4];

    const int tid  = threadIdx.x;
    const int lane = tid & 31;
    const int w    = tid >> 5;
    const int tx   = lane & 3;   // h-chunk
    const int ty   = lane >> 2;  // b-subtile
    const int wb   = w * 32;
    const int g0   = blockIdx.x * GPB;

    // ---- day transpose, once per CTA ----
    {
        const float4* dp = reinterpret_cast<const float4*>(day + tid * C);
#pragma unroll
        for (int j = 0; j < C / 4; ++j) {
            float4 v = dp[j];
            s_xd[4 * j + 0][tid] = v.x; s_xd[4 * j + 1][tid] = v.y;
            s_xd[4 * j + 2][tid] = v.z; s_xd[4 * j + 3][tid] = v.w;
        }
    }

    // ---- prefetch items(g0) into registers ----
    float4 it[8];
    {
        const float4* ip = reinterpret_cast<const float4*>(items + ((size_t)tid * G + g0) * V);
#pragma unroll
        for (int j = 0; j < 8; ++j) it[j] = ip[j];
    }

    int p = 0;
    for (int gg = 0; gg < GPB; ++gg) {
        const int g = g0 + gg;

        // ---- issue weight LDGs for g (coalesced; wait lands at their STS) ----
        float4 wd[2];
        {
            const float4* ptr = reinterpret_cast<const float4*>(W1_day + (size_t)g * H * C);
#pragma unroll
            for (int r = 0; r < 2; ++r) wd[r] = ptr[r * THREADS + tid];
        }
        float4 wv[4];
        {
            const float4* ptr = reinterpret_cast<const float4*>(W1_var + (size_t)g * H * V);
#pragma unroll
            for (int r = 0; r < 4; ++r) wv[r] = ptr[r * THREADS + tid];
        }
        float4 w2r; const bool has_w2 = tid < (O * H) / 4;
        if (has_w2) w2r = reinterpret_cast<const float4*>(W2 + (size_t)g * O * H)[tid];
        float4 b1r; const bool has_b1 = tid < H / 4;
        if (has_b1) b1r = reinterpret_cast<const float4*>(b1 + (size_t)g * H)[tid];
        float4 b2r;
        if (tid == 0) b2r = reinterpret_cast<const float4*>(b2 + (size_t)g * O)[0];

        // ---- STS items(g) into buffer p (prev compute reads p^1 -> no race, pre-sync OK) ----
#pragma unroll
        for (int j = 0; j < 8; ++j) {
            s_xi[p][4 * j + 0][tid] = it[j].x; s_xi[p][4 * j + 1][tid] = it[j].y;
            s_xi[p][4 * j + 2][tid] = it[j].z; s_xi[p][4 * j + 3][tid] = it[j].w;
        }

        // ---- prefetch items(g+1); drains under the fc1 compute below ----
        {
            const int gn = (g + 1 < G) ? (g + 1) : (G - 1);
            const float4* ip = reinterpret_cast<const float4*>(items + ((size_t)tid * G + gn) * V);
#pragma unroll
            for (int j = 0; j < 8; ++j) it[j] = ip[j];
        }

        __syncthreads();  // prev compute done with s_w1 (and this group's s_xi STS visible)

        // ---- STS weights ----
#pragma unroll
        for (int r = 0; r < 2; ++r) {
            int i4 = r * THREADS + tid;
            int h = i4 >> 2, c = (i4 << 2) & (C - 1);
            s_w1[c + 0][h] = wd[r].x; s_w1[c + 1][h] = wd[r].y;
            s_w1[c + 2][h] = wd[r].z; s_w1[c + 3][h] = wd[r].w;
        }
#pragma unroll
        for (int r = 0; r < 4; ++r) {
            int i4 = r * THREADS + tid;
            int h = i4 >> 3, v = (i4 << 2) & (V - 1);
            s_w1[C + v + 0][h] = wv[r].x; s_w1[C + v + 1][h] = wv[r].y;
            s_w1[C + v + 2][h] = wv[r].z; s_w1[C + v + 3][h] = wv[r].w;
        }
        if (has_w2) {
            int o = tid >> 4, hh = (tid << 2) & (H - 1);
            *reinterpret_cast<float4*>(&s_w2[o][hh]) = w2r;
        }
        if (has_b1) *reinterpret_cast<float4*>(&s_b1[tid * 4]) = b1r;
        if (tid == 0) *reinterpret_cast<float4*>(&s_b2[0]) = b2r;
        __syncthreads();

        // ---- fc1: acc[r][p] packed over h-pairs; init with b1 ----
        u64 acc[4][8];
        {
            ulonglong2 i0 = *reinterpret_cast<const ulonglong2*>(&s_b1[tx * 8]);
            ulonglong2 i1 = *reinterpret_cast<const ulonglong2*>(&s_b1[tx * 8 + 4]);
            ulonglong2 i2 = *reinterpret_cast<const ulonglong2*>(&s_b1[32 + tx * 8]);
            ulonglong2 i3 = *reinterpret_cast<const ulonglong2*>(&s_b1[32 + tx * 8 + 4]);
            u64 q[8] = {i0.x, i0.y, i1.x, i1.y, i2.x, i2.y, i3.x, i3.y};
#pragma unroll
            for (int r = 0; r < 4; ++r)
#pragma unroll
                for (int pp = 0; pp < 8; ++pp) acc[r][pp] = q[pp];
        }

#pragma unroll
        for (int k = 0; k < C; ++k) {
            float4 xv = *reinterpret_cast<const float4*>(&s_xd[k][wb + ty * 4]);
            ulonglong2 wA = *reinterpret_cast<const ulonglong2*>(&s_w1[k][tx * 8]);
            ulonglong2 wB = *reinterpret_cast<const ulonglong2*>(&s_w1[k][tx * 8 + 4]);
            ulonglong2 wC = *reinterpret_cast<const ulonglong2*>(&s_w1[k][32 + tx * 8]);
            ulonglong2 wD = *reinterpret_cast<const ulonglong2*>(&s_w1[k][32 + tx * 8 + 4]);
            u64 wp[8] = {wA.x, wA.y, wB.x, wB.y, wC.x, wC.y, wD.x, wD.y};
            u64 xb[4] = {bcast2(xv.x), bcast2(xv.y), bcast2(xv.z), bcast2(xv.w)};
#pragma unroll
            for (int r = 0; r < 4; ++r)
#pragma unroll
                for (int pp = 0; pp < 8; ++pp)
                    acc[r][pp] = ffma2(wp[pp], xb[r], acc[r][pp]);
        }
#pragma unroll 8
        for (int k = 0; k < V; ++k) {
            float4 xv = *reinterpret_cast<const float4*>(&s_xi[p][k][wb + ty * 4]);
            ulonglong2 wA = *reinterpret_cast<const ulonglong2*>(&s_w1[C + k][tx * 8]);
            ulonglong2 wB = *reinterpret_cast<const ulonglong2*>(&s_w1[C + k][tx * 8 + 4]);
            ulonglong2 wC = *reinterpret_cast<const ulonglong2*>(&s_w1[C + k][32 + tx * 8]);
            ulonglong2 wD = *reinterpret_cast<const ulonglong2*>(&s_w1[C + k][32 + tx * 8 + 4]);
            u64 wp[8] = {wA.x, wA.y, wB.x, wB.y, wC.x, wC.y, wD.x, wD.y};
            u64 xb[4] = {bcast2(xv.x), bcast2(xv.y), bcast2(xv.z), bcast2(xv.w)};
#pragma unroll
            for (int r = 0; r < 4; ++r)
#pragma unroll
                for (int pp = 0; pp < 8; ++pp)
                    acc[r][pp] = ffma2(wp[pp], xb[r], acc[r][pp]);
        }

        // ---- ReLU ----
#pragma unroll
        for (int r = 0; r < 4; ++r)
#pragma unroll
            for (int pp = 0; pp < 8; ++pp) {
                float2 v = unpack2(acc[r][pp]);
                acc[r][pp] = pack2(fmaxf(v.x, 0.0f), fmaxf(v.y, 0.0f));
            }

        // ---- fc2: per-thread partial over its 16 h ----
        float y[4][4];
#pragma unroll
        for (int o = 0; o < 4; ++o) {
            ulonglong2 a  = *reinterpret_cast<const ulonglong2*>(&s_w2[o][tx * 8]);
            ulonglong2 b_ = *reinterpret_cast<const ulonglong2*>(&s_w2[o][tx * 8 + 4]);
            ulonglong2 c_ = *reinterpret_cast<const ulonglong2*>(&s_w2[o][32 + tx * 8]);
            ulonglong2 d_ = *reinterpret_cast<const ulonglong2*>(&s_w2[o][32 + tx * 8 + 4]);
            u64 wq[8] = {a.x, a.y, b_.x, b_.y, c_.x, c_.y, d_.x, d_.y};
#pragma unroll
            for (int r = 0; r < 4; ++r) {
                u64 ps = 0ull;
#pragma unroll
                for (int pp = 0; pp < 8; ++pp) ps = ffma2(acc[r][pp], wq[pp], ps);
                float2 v = unpack2(ps);
                y[r][o] = v.x + v.y;
            }
        }

        // ---- allreduce over the tx-quad ----
#pragma unroll
        for (int r = 0; r < 4; ++r)
#pragma unroll
            for (int o = 0; o < 4; ++o) {
                y[r][o] += __shfl_xor_sync(0xffffffffu, y[r][o], 1);
                y[r][o] += __shfl_xor_sync(0xffffffffu, y[r][o], 2);
            }

        float4 bb = *reinterpret_cast<const float4*>(&s_b2[0]);
        const int brow = wb + ty * 4 + tx;
        float4 o4;
        if (tx == 0)
            o4 = make_float4(y[0][0] + bb.x, y[0][1] + bb.y, y[0][2] + bb.z, y[0][3] + bb.w);
        else if (tx == 1)
            o4 = make_float4(y[1][0] + bb.x, y[1][1] + bb.y, y[1][2] + bb.z, y[1][3] + bb.w);
        else if (tx == 2)
            o4 = make_float4(y[2][0] + bb.x, y[2][1] + bb.y, y[2][2] + bb.z, y[2][3] + bb.w);
        else
            o4 = make_float4(y[3][0] + bb.x, y[3][1] + bb.y, y[3][2] + bb.z, y[3][3] + bb.w);

        reinterpret_cast<float4*>(out)[(size_t)brow * G + g] = o4;

        p ^= 1;
    }
}

extern "C" void kernel_launch(void* const* d_in, const int* in_sizes, int n_in,
                              void* d_out, int out_size) {
    const float* day    = (const float*)d_in[0];
    const float* items  = (const float*)d_in[1];
    const float* W1_day = (const float*)d_in[2];
    const float* W1_var = (const float*)d_in[3];
    const float* b1     = (const float*)d_in[4];
    const float* W2     = (const float*)d_in[5];
    const float* b2     = (const float*)d_in[6];
    float* out = (float*)d_out;

    splitmlp_kernel<<<G / GPB, THREADS>>>(day, items, W1_day, W1_var, b1, W2, b2, out);
}